// round 3
// baseline (speedup 1.0000x reference)
#include <cuda_runtime.h>
#include <cuda_bf16.h>
#include <cstdint>
#include <math.h>

// Block_36455682408804: transformer block  B=16 T=1024 D=128 H=8 HS=16 FF=512
#define BT_TOTAL 16384
#define DMODEL   128
#define FFDIM    512
#define NQKV     384

// ---------------------------------------------------------------------------
// scratch (device globals: allocation-free, graph-capturable)
// ---------------------------------------------------------------------------
__device__ float g_qkv[BT_TOTAL * NQKV];
__device__ float g_att[BT_TOTAL * DMODEL];
__device__ float g_x1 [BT_TOTAL * DMODEL];
__device__ float g_hid[BT_TOTAL * FFDIM];
__device__ float g_bqkv[NQKV];
__device__ __nv_bfloat16 g_wqkv_h[NQKV * DMODEL], g_wqkv_l[NQKV * DMODEL];   // [N=384, K=128]
__device__ __nv_bfloat16 g_wp_h[DMODEL * DMODEL], g_wp_l[DMODEL * DMODEL];   // [128,128]
__device__ __nv_bfloat16 g_w1_h[FFDIM * DMODEL],  g_w1_l[FFDIM * DMODEL];    // [512,128]
__device__ __nv_bfloat16 g_w2_h[DMODEL * FFDIM],  g_w2_l[DMODEL * FFDIM];    // [128,512]

__device__ __forceinline__ void split_bf(float v, __nv_bfloat16& h, __nv_bfloat16& l) {
    h = __float2bfloat16(v);
    l = __float2bfloat16(v - __bfloat162float(h));
}

__device__ __forceinline__ uint32_t smem_u32(const void* p) {
    uint32_t a;
    asm("{ .reg .u64 t; cvta.to.shared.u64 t, %1; cvt.u32.u64 %0, t; }" : "=r"(a) : "l"(p));
    return a;
}
__device__ __forceinline__ void ldsm4(uint32_t addr, uint32_t* r) {
    asm volatile("ldmatrix.sync.aligned.m8n8.x4.shared.b16 {%0,%1,%2,%3}, [%4];"
                 : "=r"(r[0]), "=r"(r[1]), "=r"(r[2]), "=r"(r[3]) : "r"(addr));
}
__device__ __forceinline__ void mma_bf16(float* d, const uint32_t* a, uint32_t b0, uint32_t b1) {
    asm volatile("mma.sync.aligned.m16n8k16.row.col.f32.bf16.bf16.f32 "
                 "{%0,%1,%2,%3}, {%4,%5,%6,%7}, {%8,%9}, {%0,%1,%2,%3};"
                 : "+f"(d[0]), "+f"(d[1]), "+f"(d[2]), "+f"(d[3])
                 : "r"(a[0]), "r"(a[1]), "r"(a[2]), "r"(a[3]), "r"(b0), "r"(b1));
}
__device__ __forceinline__ float gelu_f(float v) {
    return 0.5f * v * (1.f + erff(v * 0.7071067811865475f));
}

// ---------------------------------------------------------------------------
// pack weights: transpose to [N,K] and split into bf16 hi/lo
// ---------------------------------------------------------------------------
__global__ void pack_kernel(const float* __restrict__ Wq, const float* __restrict__ bq,
                            const float* __restrict__ Wk, const float* __restrict__ bk,
                            const float* __restrict__ Wv, const float* __restrict__ bv,
                            const float* __restrict__ Wp, const float* __restrict__ W1,
                            const float* __restrict__ W2)
{
    int i0 = blockIdx.x * blockDim.x + threadIdx.x;
    int stride = gridDim.x * blockDim.x;
    for (int i = i0; i < NQKV * DMODEL; i += stride) {           // qkv [384,128]
        int n = i >> 7, k = i & 127;
        float v;
        if (n < 128)      v = Wq[((n >> 4) << 11) + k * 16 + (n & 15)];
        else if (n < 256) { int m = n - 128; v = Wk[((m >> 4) << 11) + k * 16 + (m & 15)]; }
        else              { int m = n - 256; v = Wv[((m >> 4) << 11) + k * 16 + (m & 15)]; }
        split_bf(v, g_wqkv_h[i], g_wqkv_l[i]);
    }
    for (int i = i0; i < DMODEL * DMODEL; i += stride) {         // wp [128,128]
        int n = i >> 7, k = i & 127;
        split_bf(Wp[k * 128 + n], g_wp_h[i], g_wp_l[i]);
    }
    for (int i = i0; i < FFDIM * DMODEL; i += stride) {          // w1 [512,128]
        int n = i >> 7, k = i & 127;
        split_bf(W1[k * 512 + n], g_w1_h[i], g_w1_l[i]);
    }
    for (int i = i0; i < DMODEL * FFDIM; i += stride) {          // w2 [128,512]
        int n = i >> 9, k = i & 511;
        split_bf(W2[k * 128 + n], g_w2_h[i], g_w2_l[i]);
    }
    for (int i = i0; i < NQKV; i += stride)
        g_bqkv[i] = (i < 128) ? bq[i] : (i < 256 ? bk[i - 128] : bv[i - 256]);
}

// ---------------------------------------------------------------------------
// HMMA GEMM: C[M,N] 128x128 tile per CTA, split-bf16 x3 accumulate.
//  A fp32 [M,lda]; B prepacked bf16 hi/lo [Ntot,K] (K-major).
//  mode 0: +bias   mode 1: +bias,gelu   mode 2: +bias+resid+LayerNorm (N=128)
// 8 warps: warp grid 4(m) x 2(n), warp tile 32x64. K chunked by 64.
// smem tiles: A_h/A_l/B_h/B_l each 128 rows x 128B (XOR-swizzled).
// ---------------------------------------------------------------------------
#define SM_AH 0
#define SM_AL 16384
#define SM_BH 32768
#define SM_BL 49152
#define SM_CS 0          // mode-2 C tile reuses A/B region: 128 x 132 floats
#define SM_BIAS 67584
#define SM_G    68096
#define SM_BE   68608
#define SM_TOTAL 69120

__global__ __launch_bounds__(256)
void gemm_mma(const float* __restrict__ A, int lda, int K,
              const __nv_bfloat16* __restrict__ Bh, const __nv_bfloat16* __restrict__ Bl,
              const float* __restrict__ bias, const float* __restrict__ resid,
              const float* __restrict__ gamma, const float* __restrict__ beta,
              float* __restrict__ C, int ldc, int mode)
{
    extern __shared__ unsigned char smraw[];
    const uint32_t smem_base = smem_u32(smraw);
    float* sBias = (float*)(smraw + SM_BIAS);
    float* sG    = (float*)(smraw + SM_G);
    float* sBe   = (float*)(smraw + SM_BE);
    float* Cs    = (float*)(smraw + SM_CS);

    const int tid = threadIdx.x;
    const int wid = tid >> 5, lane = tid & 31;
    const int m0 = blockIdx.x * 128, n0 = blockIdx.y * 128;
    const int wm = (wid & 3) * 32, wn = (wid >> 2) * 64;

    if (tid < 128) {
        sBias[tid] = bias[n0 + tid];
        if (mode == 2) { sG[tid] = gamma[tid]; sBe[tid] = beta[tid]; }
    }

    // per-lane ldmatrix geometry: q = lane>>3 selects the 8x8 sub-matrix
    const int q = lane >> 3, rin = lane & 7;
    const int rowA0 = wm + (q & 1) * 8 + rin;        // + i*16
    const int kqoff = (q >> 1) * 16;                  // byte offset within k16 (two 8-col halves)

    // staging geometry
    const int sr = tid >> 1, sh = tid & 1;            // row, k-half(32)
    const uint32_t swmask_s = (uint32_t)(sr & 7) << 4;

    float acc[2][8][4];
    #pragma unroll
    for (int i = 0; i < 2; ++i)
        #pragma unroll
        for (int j = 0; j < 8; ++j)
            #pragma unroll
            for (int e = 0; e < 4; ++e) acc[i][j][e] = 0.f;

    const int nchunks = K >> 6;
    for (int c = 0; c < nchunks; ++c) {
        const int kc = c << 6;
        // ---- stage A: fp32 -> bf16 hi/lo, swizzled ----
        {
            const float* arow = A + (size_t)(m0 + sr) * lda + kc + sh * 32;
            #pragma unroll
            for (int g = 0; g < 4; ++g) {
                float4 f0 = *(const float4*)(arow + g * 8);
                float4 f1 = *(const float4*)(arow + g * 8 + 4);
                float v[8] = {f0.x, f0.y, f0.z, f0.w, f1.x, f1.y, f1.z, f1.w};
                unsigned short hh[8], ll[8];
                #pragma unroll
                for (int e = 0; e < 8; ++e) {
                    __nv_bfloat16 bh, bl; split_bf(v[e], bh, bl);
                    hh[e] = __bfloat16_as_ushort(bh); ll[e] = __bfloat16_as_ushort(bl);
                }
                uint4 uh, ul;
                uh.x = hh[0] | (uint32_t)hh[1] << 16; uh.y = hh[2] | (uint32_t)hh[3] << 16;
                uh.z = hh[4] | (uint32_t)hh[5] << 16; uh.w = hh[6] | (uint32_t)hh[7] << 16;
                ul.x = ll[0] | (uint32_t)ll[1] << 16; ul.y = ll[2] | (uint32_t)ll[3] << 16;
                ul.z = ll[4] | (uint32_t)ll[5] << 16; ul.w = ll[6] | (uint32_t)ll[7] << 16;
                uint32_t kb = (uint32_t)((sh * 32 + g * 8) * 2);
                uint32_t off = (uint32_t)sr * 128 + (kb ^ swmask_s);
                *(uint4*)(smraw + SM_AH + off) = uh;
                *(uint4*)(smraw + SM_AL + off) = ul;
            }
        }
        // ---- stage B: bf16 copy, swizzled ----
        {
            const __nv_bfloat16* bhrow = Bh + (size_t)(n0 + sr) * K + kc + sh * 32;
            const __nv_bfloat16* blrow = Bl + (size_t)(n0 + sr) * K + kc + sh * 32;
            #pragma unroll
            for (int g = 0; g < 4; ++g) {
                uint32_t kb = (uint32_t)((sh * 32 + g * 8) * 2);
                uint32_t off = (uint32_t)sr * 128 + (kb ^ swmask_s);
                *(uint4*)(smraw + SM_BH + off) = *(const uint4*)(bhrow + g * 8);
                *(uint4*)(smraw + SM_BL + off) = *(const uint4*)(blrow + g * 8);
            }
        }
        __syncthreads();
        // ---- 4 k16 steps ----
        #pragma unroll
        for (int ks = 0; ks < 4; ++ks) {
            const uint32_t kb = (uint32_t)(ks * 32 + kqoff);
            uint32_t ah[2][4], al[2][4], bh[8][2], bl[8][2];
            #pragma unroll
            for (int i = 0; i < 2; ++i) {
                uint32_t row = (uint32_t)(rowA0 + i * 16);
                uint32_t off = row * 128 + (kb ^ ((row & 7) << 4));
                ldsm4(smem_base + SM_AH + off, ah[i]);
                ldsm4(smem_base + SM_AL + off, al[i]);
            }
            #pragma unroll
            for (int j2 = 0; j2 < 4; ++j2) {
                uint32_t row = (uint32_t)(wn + j2 * 16 + (q & 1) * 8 + rin);
                uint32_t off = row * 128 + (kb ^ ((row & 7) << 4));
                uint32_t r4[4];
                ldsm4(smem_base + SM_BH + off, r4);
                bh[2*j2][0] = r4[0]; bh[2*j2][1] = r4[2];
                bh[2*j2+1][0] = r4[1]; bh[2*j2+1][1] = r4[3];
                ldsm4(smem_base + SM_BL + off, r4);
                bl[2*j2][0] = r4[0]; bl[2*j2][1] = r4[2];
                bl[2*j2+1][0] = r4[1]; bl[2*j2+1][1] = r4[3];
            }
            #pragma unroll
            for (int i = 0; i < 2; ++i)
                #pragma unroll
                for (int j = 0; j < 8; ++j) {
                    mma_bf16(acc[i][j], ah[i], bh[j][0], bh[j][1]);
                    mma_bf16(acc[i][j], ah[i], bl[j][0], bl[j][1]);
                    mma_bf16(acc[i][j], al[i], bh[j][0], bh[j][1]);
                }
        }
        __syncthreads();
    }

    // ---- epilogue ----
    if (mode != 2) {
        #pragma unroll
        for (int i = 0; i < 2; ++i)
            #pragma unroll
            for (int j = 0; j < 8; ++j) {
                int cp = wn + j * 8 + (lane & 3) * 2;
                float b0 = sBias[cp], b1 = sBias[cp + 1];
                int r0 = m0 + wm + i * 16 + (lane >> 2);
                float v0 = acc[i][j][0] + b0, v1 = acc[i][j][1] + b1;
                float v2 = acc[i][j][2] + b0, v3 = acc[i][j][3] + b1;
                if (mode == 1) { v0 = gelu_f(v0); v1 = gelu_f(v1); v2 = gelu_f(v2); v3 = gelu_f(v3); }
                *(float2*)(C + (size_t)r0 * ldc + n0 + cp)       = make_float2(v0, v1);
                *(float2*)(C + (size_t)(r0 + 8) * ldc + n0 + cp) = make_float2(v2, v3);
            }
    } else {
        #pragma unroll
        for (int i = 0; i < 2; ++i)
            #pragma unroll
            for (int j = 0; j < 8; ++j) {
                int cp = wn + j * 8 + (lane & 3) * 2;
                float b0 = sBias[cp], b1 = sBias[cp + 1];
                int r0 = wm + i * 16 + (lane >> 2);
                Cs[r0 * 132 + cp]       = acc[i][j][0] + b0;
                Cs[r0 * 132 + cp + 1]   = acc[i][j][1] + b1;
                Cs[(r0 + 8) * 132 + cp]     = acc[i][j][2] + b0;
                Cs[(r0 + 8) * 132 + cp + 1] = acc[i][j][3] + b1;
            }
        __syncthreads();
        // LayerNorm: warp w handles rows w*16..w*16+15; lane covers 4 cols
        for (int rr = 0; rr < 16; ++rr) {
            int row = wid * 16 + rr;
            const float* cr = Cs + row * 132 + lane * 4;
            float2 p0 = *(const float2*)(cr);
            float2 p1 = *(const float2*)(cr + 2);
            const float4 rv = *(const float4*)(resid + (size_t)(m0 + row) * 128 + lane * 4);
            float v0 = p0.x + rv.x, v1 = p0.y + rv.y, v2 = p1.x + rv.z, v3 = p1.y + rv.w;
            float s  = v0 + v1 + v2 + v3;
            float sq = v0 * v0 + v1 * v1 + v2 * v2 + v3 * v3;
            #pragma unroll
            for (int off = 16; off > 0; off >>= 1) {
                s  += __shfl_xor_sync(0xffffffffu, s,  off);
                sq += __shfl_xor_sync(0xffffffffu, sq, off);
            }
            float mean = s * (1.f / 128.f);
            float var  = sq * (1.f / 128.f) - mean * mean;
            float is   = rsqrtf(var + 1e-5f);
            int cbase = lane * 4;
            float o0 = (v0 - mean) * is * sG[cbase]     + sBe[cbase];
            float o1 = (v1 - mean) * is * sG[cbase + 1] + sBe[cbase + 1];
            float o2 = (v2 - mean) * is * sG[cbase + 2] + sBe[cbase + 2];
            float o3 = (v3 - mean) * is * sG[cbase + 3] + sBe[cbase + 3];
            *(float4*)(C + (size_t)(m0 + row) * 128 + cbase) = make_float4(o0, o1, o2, o3);
        }
    }
}

// ---------------------------------------------------------------------------
// Causal attention fp32, streaming softmax, 128-row K/V tiles (16KB smem, high occ)
// grid = B*H*4 (quarter of rows); block = 256; warp owns 32 query rows.
// ---------------------------------------------------------------------------
__global__ __launch_bounds__(256) void attn_kernel(const float* __restrict__ QKV, float* __restrict__ Att)
{
    extern __shared__ unsigned char smraw[];
    float4* kf = (float4*)smraw;            // [128*4]
    float4* vf = (float4*)smraw + 512;      // [128*4]
    const int quarter = blockIdx.x & 3;
    const int bh = blockIdx.x >> 2;
    const int b = bh >> 3, h = bh & 7;
    const int bT = b << 10;
    const int tid = threadIdx.x;
    const int w = tid >> 5, lane = tid & 31;
    const int t_base = (quarter << 8) + (w << 5);
    const int t = t_base + lane;
    const int myend = t_base + 32;

    const float* qp = QKV + (size_t)(bT + t) * 384 + (h << 4);
    float4 q[4];
    q[0] = *(const float4*)(qp);     q[1] = *(const float4*)(qp + 4);
    q[2] = *(const float4*)(qp + 8); q[3] = *(const float4*)(qp + 12);

    float4 a0 = make_float4(0, 0, 0, 0), a1 = a0, a2 = a0, a3 = a0;
    float l = 0.f;

    const int ntiles = 2 * (quarter + 1);
    for (int tile = 0; tile < ntiles; ++tile) {
        const int u0 = tile << 7;
        for (int idx = tid; idx < 512; idx += 256) {
            int u = u0 + (idx >> 2), c4 = idx & 3;
            const float* base = QKV + (size_t)(bT + u) * 384 + (h << 4) + (c4 << 2);
            kf[idx] = *(const float4*)(base + 128);
            vf[idx] = *(const float4*)(base + 256);
        }
        __syncthreads();
        int lim = myend - u0; if (lim > 128) lim = 128;
        for (int lb = 0; lb < lim; lb += 8) {
            float s[8] = {0, 0, 0, 0, 0, 0, 0, 0};
            #pragma unroll
            for (int j4 = 0; j4 < 4; ++j4) {
                float4 qv = q[j4];
                #pragma unroll
                for (int uu = 0; uu < 8; ++uu) {
                    float4 kk = kf[(lb + uu) * 4 + j4];
                    s[uu] += qv.x * kk.x + qv.y * kk.y + qv.z * kk.z + qv.w * kk.w;
                }
            }
            #pragma unroll
            for (int uu = 0; uu < 8; ++uu) {
                int u = u0 + lb + uu;
                float p = (u <= t) ? __expf(s[uu] * 0.25f) : 0.f;
                l += p;
                float4 v0 = vf[(lb + uu) * 4 + 0];
                a0.x += p * v0.x; a0.y += p * v0.y; a0.z += p * v0.z; a0.w += p * v0.w;
                float4 v1 = vf[(lb + uu) * 4 + 1];
                a1.x += p * v1.x; a1.y += p * v1.y; a1.z += p * v1.z; a1.w += p * v1.w;
                float4 v2 = vf[(lb + uu) * 4 + 2];
                a2.x += p * v2.x; a2.y += p * v2.y; a2.z += p * v2.z; a2.w += p * v2.w;
                float4 v3 = vf[(lb + uu) * 4 + 3];
                a3.x += p * v3.x; a3.y += p * v3.y; a3.z += p * v3.z; a3.w += p * v3.w;
            }
        }
        __syncthreads();
    }
    float inv = 1.f / l;
    float* dst = Att + (size_t)(bT + t) * 128 + (h << 4);
    ((float4*)dst)[0] = make_float4(a0.x * inv, a0.y * inv, a0.z * inv, a0.w * inv);
    ((float4*)dst)[1] = make_float4(a1.x * inv, a1.y * inv, a1.z * inv, a1.w * inv);
    ((float4*)dst)[2] = make_float4(a2.x * inv, a2.y * inv, a2.z * inv, a2.w * inv);
    ((float4*)dst)[3] = make_float4(a3.x * inv, a3.y * inv, a3.z * inv, a3.w * inv);
}

// ---------------------------------------------------------------------------
extern "C" void kernel_launch(void* const* d_in, const int* in_sizes, int n_in,
                              void* d_out, int out_size)
{
    const float* x   = (const float*)d_in[0];
    const float* Wq  = (const float*)d_in[1];
    const float* bq  = (const float*)d_in[2];
    const float* Wk  = (const float*)d_in[3];
    const float* bk  = (const float*)d_in[4];
    const float* Wv  = (const float*)d_in[5];
    const float* bv  = (const float*)d_in[6];
    const float* Wp  = (const float*)d_in[7];
    const float* bp  = (const float*)d_in[8];
    const float* W1  = (const float*)d_in[9];
    const float* b1  = (const float*)d_in[10];
    const float* W2  = (const float*)d_in[11];
    const float* b2  = (const float*)d_in[12];
    const float* g1  = (const float*)d_in[13];
    const float* be1 = (const float*)d_in[14];
    const float* g2  = (const float*)d_in[15];
    const float* be2 = (const float*)d_in[16];
    float* out = (float*)d_out;

    float *p_qkv, *p_att, *p_x1, *p_hid, *p_bqkv;
    __nv_bfloat16 *p_wqkv_h, *p_wqkv_l, *p_wp_h, *p_wp_l, *p_w1_h, *p_w1_l, *p_w2_h, *p_w2_l;
    cudaGetSymbolAddress((void**)&p_qkv, g_qkv);
    cudaGetSymbolAddress((void**)&p_att, g_att);
    cudaGetSymbolAddress((void**)&p_x1,  g_x1);
    cudaGetSymbolAddress((void**)&p_hid, g_hid);
    cudaGetSymbolAddress((void**)&p_bqkv, g_bqkv);
    cudaGetSymbolAddress((void**)&p_wqkv_h, g_wqkv_h);
    cudaGetSymbolAddress((void**)&p_wqkv_l, g_wqkv_l);
    cudaGetSymbolAddress((void**)&p_wp_h, g_wp_h);
    cudaGetSymbolAddress((void**)&p_wp_l, g_wp_l);
    cudaGetSymbolAddress((void**)&p_w1_h, g_w1_h);
    cudaGetSymbolAddress((void**)&p_w1_l, g_w1_l);
    cudaGetSymbolAddress((void**)&p_w2_h, g_w2_h);
    cudaGetSymbolAddress((void**)&p_w2_l, g_w2_l);

    cudaFuncSetAttribute(gemm_mma, cudaFuncAttributeMaxDynamicSharedMemorySize, SM_TOTAL);

    // 1. pack weights (transpose + bf16 split)
    pack_kernel<<<256, 256>>>(Wq, bq, Wk, bk, Wv, bv, Wp, W1, W2);
    // 2. QKV: [16384,128] @ [128,384]
    gemm_mma<<<dim3(128, 3), 256, SM_TOTAL>>>(x, 128, 128, p_wqkv_h, p_wqkv_l,
                                              p_bqkv, nullptr, nullptr, nullptr,
                                              p_qkv, NQKV, 0);
    // 3. causal attention (fp32)
    attn_kernel<<<16 * 8 * 4, 256, 16384>>>(p_qkv, p_att);
    // 4. proj + bias + residual + LN1
    gemm_mma<<<dim3(128, 1), 256, SM_TOTAL>>>(p_att, 128, 128, p_wp_h, p_wp_l,
                                              bp, x, g1, be1, p_x1, DMODEL, 2);
    // 5. MLP up + exact GELU: [16384,128] @ [128,512]
    gemm_mma<<<dim3(128, 4), 256, SM_TOTAL>>>(p_x1, 128, 128, p_w1_h, p_w1_l,
                                              b1, nullptr, nullptr, nullptr,
                                              p_hid, FFDIM, 1);
    // 6. MLP down (K=512) + bias + residual + LN2 -> out
    gemm_mma<<<dim3(128, 1), 256, SM_TOTAL>>>(p_hid, 512, 512, p_w2_h, p_w2_l,
                                              b2, p_x1, g2, be2, out, DMODEL, 2);
}

// round 4
// speedup vs baseline: 1.8879x; 1.8879x over previous
#include <cuda_runtime.h>
#include <cuda_bf16.h>
#include <cstdint>
#include <math.h>

// Block_36455682408804: transformer block  B=16 T=1024 D=128 H=8 HS=16 FF=512
#define BT_TOTAL 16384
#define DMODEL   128
#define FFDIM    512
#define NQKV     384

// ---------------------------------------------------------------------------
// device-global scratch (allocation-free, graph-capturable)
// ---------------------------------------------------------------------------
__device__ float g_qkv[BT_TOTAL * NQKV];                  // fp32 q|k|v rows
__device__ float g_x1 [BT_TOTAL * DMODEL];                // fp32 (residual for MLP2)
__device__ float g_bqkv[NQKV];
__device__ __nv_bfloat16 g_xh [BT_TOTAL * DMODEL], g_xl [BT_TOTAL * DMODEL];
__device__ __nv_bfloat16 g_ath[BT_TOTAL * DMODEL], g_atl[BT_TOTAL * DMODEL];
__device__ __nv_bfloat16 g_x1h[BT_TOTAL * DMODEL], g_x1l[BT_TOTAL * DMODEL];
__device__ __nv_bfloat16 g_hih[BT_TOTAL * FFDIM],  g_hil[BT_TOTAL * FFDIM];
__device__ __nv_bfloat16 g_wqkv_h[NQKV * DMODEL],  g_wqkv_l[NQKV * DMODEL];
__device__ __nv_bfloat16 g_wp_h[DMODEL * DMODEL],  g_wp_l[DMODEL * DMODEL];
__device__ __nv_bfloat16 g_w1_h[FFDIM * DMODEL],   g_w1_l[FFDIM * DMODEL];
__device__ __nv_bfloat16 g_w2_h[DMODEL * FFDIM],   g_w2_l[DMODEL * FFDIM];

// ---------------------------------------------------------------------------
// helpers
// ---------------------------------------------------------------------------
__device__ __forceinline__ void split_bf(float v, __nv_bfloat16& h, __nv_bfloat16& l) {
    h = __float2bfloat16(v);
    l = __float2bfloat16(v - __bfloat162float(h));
}
__device__ __forceinline__ void split2(float x, float y, uint32_t& h, uint32_t& l) {
    __nv_bfloat16 xh, xl, yh, yl;
    split_bf(x, xh, xl); split_bf(y, yh, yl);
    h = (uint32_t)__bfloat16_as_ushort(xh) | ((uint32_t)__bfloat16_as_ushort(yh) << 16);
    l = (uint32_t)__bfloat16_as_ushort(xl) | ((uint32_t)__bfloat16_as_ushort(yl) << 16);
}
__device__ __forceinline__ uint32_t smem_u32(const void* p) {
    uint32_t a;
    asm("{ .reg .u64 t; cvta.to.shared.u64 t, %1; cvt.u32.u64 %0, t; }" : "=r"(a) : "l"(p));
    return a;
}
__device__ __forceinline__ void ldsm4(uint32_t addr, uint32_t* r) {
    asm volatile("ldmatrix.sync.aligned.m8n8.x4.shared.b16 {%0,%1,%2,%3}, [%4];"
                 : "=r"(r[0]), "=r"(r[1]), "=r"(r[2]), "=r"(r[3]) : "r"(addr));
}
__device__ __forceinline__ void mma_bf16(float* d, const uint32_t* a, uint32_t b0, uint32_t b1) {
    asm volatile("mma.sync.aligned.m16n8k16.row.col.f32.bf16.bf16.f32 "
                 "{%0,%1,%2,%3}, {%4,%5,%6,%7}, {%8,%9}, {%0,%1,%2,%3};"
                 : "+f"(d[0]), "+f"(d[1]), "+f"(d[2]), "+f"(d[3])
                 : "r"(a[0]), "r"(a[1]), "r"(a[2]), "r"(a[3]), "r"(b0), "r"(b1));
}
__device__ __forceinline__ float gelu_f(float v) {
    return 0.5f * v * (1.f + erff(v * 0.7071067811865475f));
}

// ---------------------------------------------------------------------------
// pack weights: transpose to [N,K], split bf16 hi/lo
// ---------------------------------------------------------------------------
__global__ void pack_kernel(const float* __restrict__ Wq, const float* __restrict__ bq,
                            const float* __restrict__ Wk, const float* __restrict__ bk,
                            const float* __restrict__ Wv, const float* __restrict__ bv,
                            const float* __restrict__ Wp, const float* __restrict__ W1,
                            const float* __restrict__ W2)
{
    int i0 = blockIdx.x * blockDim.x + threadIdx.x;
    int stride = gridDim.x * blockDim.x;
    for (int i = i0; i < NQKV * DMODEL; i += stride) {
        int n = i >> 7, k = i & 127;
        float v;
        if (n < 128)      v = Wq[((n >> 4) << 11) + k * 16 + (n & 15)];
        else if (n < 256) { int m = n - 128; v = Wk[((m >> 4) << 11) + k * 16 + (m & 15)]; }
        else              { int m = n - 256; v = Wv[((m >> 4) << 11) + k * 16 + (m & 15)]; }
        split_bf(v, g_wqkv_h[i], g_wqkv_l[i]);
    }
    for (int i = i0; i < DMODEL * DMODEL; i += stride) {
        int n = i >> 7, k = i & 127;
        split_bf(Wp[k * 128 + n], g_wp_h[i], g_wp_l[i]);
    }
    for (int i = i0; i < FFDIM * DMODEL; i += stride) {
        int n = i >> 7, k = i & 127;
        split_bf(W1[k * 512 + n], g_w1_h[i], g_w1_l[i]);
    }
    for (int i = i0; i < DMODEL * FFDIM; i += stride) {
        int n = i >> 9, k = i & 511;
        split_bf(W2[k * 128 + n], g_w2_h[i], g_w2_l[i]);
    }
    for (int i = i0; i < NQKV; i += stride)
        g_bqkv[i] = (i < 128) ? bq[i] : (i < 256 ? bk[i - 128] : bv[i - 256]);
}

// split activations x -> xh, xl
__global__ void split_x_kernel(const float* __restrict__ X,
                               __nv_bfloat16* __restrict__ Xh, __nv_bfloat16* __restrict__ Xl)
{
    int i = blockIdx.x * blockDim.x + threadIdx.x;      // float4 index
    float4 v = ((const float4*)X)[i];
    uint32_t h0, l0, h1, l1;
    split2(v.x, v.y, h0, l0); split2(v.z, v.w, h1, l1);
    ((uint2*)Xh)[i] = make_uint2(h0, h1);
    ((uint2*)Xl)[i] = make_uint2(l0, l1);
}

// ---------------------------------------------------------------------------
// HMMA GEMM, all-bf16 inputs (prepacked hi/lo). CTA tile 128x128, 8 warps
// (4m x 2n), warp tile 32x64, K chunked by 64, XOR-swizzled smem.
// flags: 1=gelu, 2=layernorm(+resid), 4=write fp32, 8=write bf16 hi/lo
// ---------------------------------------------------------------------------
#define FL_GELU 1
#define FL_LN   2
#define FL_F32  4
#define FL_BF   8

#define SM_AH 0
#define SM_AL 16384
#define SM_BH 32768
#define SM_BL 49152
#define SM_CS 0
#define SM_BIAS 67584
#define SM_G    68096
#define SM_BE   68608
#define SM_TOTAL 69120

__global__ __launch_bounds__(256, 2)
void gemm_mma(const __nv_bfloat16* __restrict__ Ah_, const __nv_bfloat16* __restrict__ Al_,
              int K,
              const __nv_bfloat16* __restrict__ Bh_, const __nv_bfloat16* __restrict__ Bl_,
              const float* __restrict__ bias, const float* __restrict__ resid,
              const float* __restrict__ gamma, const float* __restrict__ beta,
              float* __restrict__ Cf, __nv_bfloat16* __restrict__ Cbh, __nv_bfloat16* __restrict__ Cbl,
              int ldc, int flags)
{
    extern __shared__ unsigned char smraw[];
    const uint32_t smem_base = smem_u32(smraw);
    float* sBias = (float*)(smraw + SM_BIAS);
    float* sG    = (float*)(smraw + SM_G);
    float* sBe   = (float*)(smraw + SM_BE);
    float* Cs    = (float*)(smraw + SM_CS);

    const int tid = threadIdx.x;
    const int wid = tid >> 5, lane = tid & 31;
    const int m0 = blockIdx.x * 128, n0 = blockIdx.y * 128;
    const int wm = (wid & 3) * 32, wn = (wid >> 2) * 64;

    if (tid < 128) {
        sBias[tid] = bias[n0 + tid];
        if (flags & FL_LN) { sG[tid] = gamma[tid]; sBe[tid] = beta[tid]; }
    }

    const int q = lane >> 3, rin = lane & 7;
    const int rowA0 = wm + (q & 1) * 8 + rin;
    const int kqoff = (q >> 1) * 16;

    const int sr = tid >> 1, sh = tid & 1;
    const uint32_t swmask_s = (uint32_t)(sr & 7) << 4;

    float acc[2][8][4];
    #pragma unroll
    for (int i = 0; i < 2; ++i)
        #pragma unroll
        for (int j = 0; j < 8; ++j)
            #pragma unroll
            for (int e = 0; e < 4; ++e) acc[i][j][e] = 0.f;

    const int nchunks = K >> 6;
    for (int c = 0; c < nchunks; ++c) {
        const int kc = c << 6;
        const __nv_bfloat16* arh = Ah_ + (size_t)(m0 + sr) * K + kc + sh * 32;
        const __nv_bfloat16* arl = Al_ + (size_t)(m0 + sr) * K + kc + sh * 32;
        const __nv_bfloat16* brh = Bh_ + (size_t)(n0 + sr) * K + kc + sh * 32;
        const __nv_bfloat16* brl = Bl_ + (size_t)(n0 + sr) * K + kc + sh * 32;
        #pragma unroll
        for (int g = 0; g < 4; ++g) {
            uint32_t kb = (uint32_t)((sh * 32 + g * 8) * 2);
            uint32_t off = (uint32_t)sr * 128 + (kb ^ swmask_s);
            *(uint4*)(smraw + SM_AH + off) = *(const uint4*)(arh + g * 8);
            *(uint4*)(smraw + SM_AL + off) = *(const uint4*)(arl + g * 8);
            *(uint4*)(smraw + SM_BH + off) = *(const uint4*)(brh + g * 8);
            *(uint4*)(smraw + SM_BL + off) = *(const uint4*)(brl + g * 8);
        }
        __syncthreads();
        #pragma unroll
        for (int ks = 0; ks < 4; ++ks) {
            const uint32_t kb = (uint32_t)(ks * 32 + kqoff);
            uint32_t ah[2][4], al[2][4], bh[8][2], bl[8][2];
            #pragma unroll
            for (int i = 0; i < 2; ++i) {
                uint32_t row = (uint32_t)(rowA0 + i * 16);
                uint32_t off = row * 128 + (kb ^ ((row & 7) << 4));
                ldsm4(smem_base + SM_AH + off, ah[i]);
                ldsm4(smem_base + SM_AL + off, al[i]);
            }
            #pragma unroll
            for (int j2 = 0; j2 < 4; ++j2) {
                uint32_t row = (uint32_t)(wn + j2 * 16 + (q & 1) * 8 + rin);
                uint32_t off = row * 128 + (kb ^ ((row & 7) << 4));
                uint32_t r4[4];
                ldsm4(smem_base + SM_BH + off, r4);
                bh[2*j2][0] = r4[0]; bh[2*j2][1] = r4[2];
                bh[2*j2+1][0] = r4[1]; bh[2*j2+1][1] = r4[3];
                ldsm4(smem_base + SM_BL + off, r4);
                bl[2*j2][0] = r4[0]; bl[2*j2][1] = r4[2];
                bl[2*j2+1][0] = r4[1]; bl[2*j2+1][1] = r4[3];
            }
            #pragma unroll
            for (int i = 0; i < 2; ++i)
                #pragma unroll
                for (int j = 0; j < 8; ++j) {
                    mma_bf16(acc[i][j], ah[i], bh[j][0], bh[j][1]);
                    mma_bf16(acc[i][j], ah[i], bl[j][0], bl[j][1]);
                    mma_bf16(acc[i][j], al[i], bh[j][0], bh[j][1]);
                }
        }
        __syncthreads();
    }

    if (!(flags & FL_LN)) {
        #pragma unroll
        for (int i = 0; i < 2; ++i)
            #pragma unroll
            for (int j = 0; j < 8; ++j) {
                int cp = wn + j * 8 + (lane & 3) * 2;
                float b0 = sBias[cp], b1 = sBias[cp + 1];
                int r0 = m0 + wm + i * 16 + (lane >> 2);
                float v0 = acc[i][j][0] + b0, v1 = acc[i][j][1] + b1;
                float v2 = acc[i][j][2] + b0, v3 = acc[i][j][3] + b1;
                if (flags & FL_GELU) { v0 = gelu_f(v0); v1 = gelu_f(v1); v2 = gelu_f(v2); v3 = gelu_f(v3); }
                if (flags & FL_F32) {
                    *(float2*)(Cf + (size_t)r0 * ldc + n0 + cp)       = make_float2(v0, v1);
                    *(float2*)(Cf + (size_t)(r0 + 8) * ldc + n0 + cp) = make_float2(v2, v3);
                }
                if (flags & FL_BF) {
                    uint32_t hh, ll;
                    split2(v0, v1, hh, ll);
                    *(uint32_t*)(Cbh + (size_t)r0 * ldc + n0 + cp) = hh;
                    *(uint32_t*)(Cbl + (size_t)r0 * ldc + n0 + cp) = ll;
                    split2(v2, v3, hh, ll);
                    *(uint32_t*)(Cbh + (size_t)(r0 + 8) * ldc + n0 + cp) = hh;
                    *(uint32_t*)(Cbl + (size_t)(r0 + 8) * ldc + n0 + cp) = ll;
                }
            }
    } else {
        #pragma unroll
        for (int i = 0; i < 2; ++i)
            #pragma unroll
            for (int j = 0; j < 8; ++j) {
                int cp = wn + j * 8 + (lane & 3) * 2;
                float b0 = sBias[cp], b1 = sBias[cp + 1];
                int r0 = wm + i * 16 + (lane >> 2);
                Cs[r0 * 132 + cp]           = acc[i][j][0] + b0;
                Cs[r0 * 132 + cp + 1]       = acc[i][j][1] + b1;
                Cs[(r0 + 8) * 132 + cp]     = acc[i][j][2] + b0;
                Cs[(r0 + 8) * 132 + cp + 1] = acc[i][j][3] + b1;
            }
        __syncthreads();
        for (int rr = 0; rr < 16; ++rr) {
            int row = wid * 16 + rr;
            const float* cr = Cs + row * 132 + lane * 4;
            float2 p0 = *(const float2*)(cr);
            float2 p1 = *(const float2*)(cr + 2);
            const float4 rv = *(const float4*)(resid + (size_t)(m0 + row) * 128 + lane * 4);
            float v0 = p0.x + rv.x, v1 = p0.y + rv.y, v2 = p1.x + rv.z, v3 = p1.y + rv.w;
            float s  = v0 + v1 + v2 + v3;
            float sq = v0 * v0 + v1 * v1 + v2 * v2 + v3 * v3;
            #pragma unroll
            for (int off = 16; off > 0; off >>= 1) {
                s  += __shfl_xor_sync(0xffffffffu, s,  off);
                sq += __shfl_xor_sync(0xffffffffu, sq, off);
            }
            float mean = s * (1.f / 128.f);
            float var  = sq * (1.f / 128.f) - mean * mean;
            float is   = rsqrtf(var + 1e-5f);
            int cb = lane * 4;
            float o0 = (v0 - mean) * is * sG[cb]     + sBe[cb];
            float o1 = (v1 - mean) * is * sG[cb + 1] + sBe[cb + 1];
            float o2 = (v2 - mean) * is * sG[cb + 2] + sBe[cb + 2];
            float o3 = (v3 - mean) * is * sG[cb + 3] + sBe[cb + 3];
            size_t base = (size_t)(m0 + row) * 128 + cb;
            if (flags & FL_F32)
                *(float4*)(Cf + base) = make_float4(o0, o1, o2, o3);
            if (flags & FL_BF) {
                uint32_t hh, ll;
                split2(o0, o1, hh, ll);
                *(uint32_t*)(Cbh + base) = hh; *(uint32_t*)(Cbl + base) = ll;
                split2(o2, o3, hh, ll);
                *(uint32_t*)(Cbh + base + 2) = hh; *(uint32_t*)(Cbl + base + 2) = ll;
            }
        }
    }
}

// ---------------------------------------------------------------------------
// Flash-style causal attention via HMMA, split-bf16 (3 mmas per product).
// grid = (8 qtiles, 128 bh); 128 threads = 4 warps; warp owns 32 query rows.
// KV processed in 64-key tiles. No-max streaming softmax (scores are O(1)).
// Emits attention output directly as bf16 hi/lo for the proj GEMM.
// ---------------------------------------------------------------------------
__global__ __launch_bounds__(128)
void attn_mma(const float* __restrict__ QKV,
              __nv_bfloat16* __restrict__ Oh, __nv_bfloat16* __restrict__ Ol)
{
    __shared__ __align__(16) unsigned char sm[16896];
    float* sQ = (float*)sm;                                   // 128x16 fp32
    __nv_bfloat16* sKh = (__nv_bfloat16*)(sm + 8192);         // 64x16
    __nv_bfloat16* sKl = (__nv_bfloat16*)(sm + 10240);
    __nv_bfloat16* sVh = (__nv_bfloat16*)(sm + 12288);        // 16x72 (transposed, padded)
    __nv_bfloat16* sVl = (__nv_bfloat16*)(sm + 14592);

    const int qt = blockIdx.x;           // 0..7
    const int bh = blockIdx.y;           // 0..127
    const int b = bh >> 3, h = bh & 7;
    const int bT = b << 10;
    const int q0 = qt << 7;
    const int tid = threadIdx.x;
    const int w = tid >> 5, lane = tid & 31;
    const int r4 = lane >> 2, c2 = (lane & 3) * 2, lane3 = lane & 3;
    const int W0 = q0 + (w << 5);

    // stage Q tile
    {
        const float* src = QKV + (size_t)(bT + q0 + tid) * 384 + (h << 4);
        float4 f0 = *(const float4*)src;
        float4 f1 = *(const float4*)(src + 4);
        float4 f2 = *(const float4*)(src + 8);
        float4 f3 = *(const float4*)(src + 12);
        float* d = sQ + tid * 16;
        *(float4*)(d)      = f0; *(float4*)(d + 4)  = f1;
        *(float4*)(d + 8)  = f2; *(float4*)(d + 12) = f3;
    }
    __syncthreads();

    // Q fragments (hi/lo)
    uint32_t aqh[2][4], aql[2][4];
    #pragma unroll
    for (int i = 0; i < 2; ++i) {
        int rA = (w << 5) + i * 16 + r4, rB = rA + 8;
        float2 v;
        v = *(float2*)&sQ[rA * 16 + c2];     split2(v.x, v.y, aqh[i][0], aql[i][0]);
        v = *(float2*)&sQ[rB * 16 + c2];     split2(v.x, v.y, aqh[i][1], aql[i][1]);
        v = *(float2*)&sQ[rA * 16 + c2 + 8]; split2(v.x, v.y, aqh[i][2], aql[i][2]);
        v = *(float2*)&sQ[rB * 16 + c2 + 8]; split2(v.x, v.y, aqh[i][3], aql[i][3]);
    }
    __syncthreads();

    float o[2][2][4];
    #pragma unroll
    for (int i = 0; i < 2; ++i)
        #pragma unroll
        for (int n = 0; n < 2; ++n)
            #pragma unroll
            for (int e = 0; e < 4; ++e) o[i][n][e] = 0.f;
    float lsum[2][2] = {{0.f, 0.f}, {0.f, 0.f}};

    const int ntiles = (qt + 1) << 1;
    for (int tile = 0; tile < ntiles; ++tile) {
        const int u0 = tile << 6;
        // stage 64 keys of K and V (bf16 split; V transposed)
        if (tid < 64) {
            const float* src = QKV + (size_t)(bT + u0 + tid) * 384 + 128 + (h << 4);
            __nv_bfloat16* dh = sKh + tid * 16;
            __nv_bfloat16* dl = sKl + tid * 16;
            #pragma unroll
            for (int e = 0; e < 16; ++e) split_bf(src[e], dh[e], dl[e]);
        } else {
            const int key = tid - 64;
            const float* src = QKV + (size_t)(bT + u0 + key) * 384 + 256 + (h << 4);
            #pragma unroll
            for (int e = 0; e < 16; ++e) split_bf(src[e], sVh[e * 72 + key], sVl[e * 72 + key]);
        }
        __syncthreads();

        if (u0 <= W0 + 31) {
            #pragma unroll
            for (int kk = 0; kk < 4; ++kk) {
                const int kbase = u0 + kk * 16;
                if (kbase > W0 + 31) break;
                // scores for 16 keys (2 n8 tiles)
                float s[2][2][4];
                #pragma unroll
                for (int i = 0; i < 2; ++i)
                    #pragma unroll
                    for (int jj = 0; jj < 2; ++jj)
                        #pragma unroll
                        for (int e = 0; e < 4; ++e) s[i][jj][e] = 0.f;
                #pragma unroll
                for (int jj = 0; jj < 2; ++jj) {
                    int n = (kk * 2 + jj) * 8 + r4;
                    const uint32_t* krh = (const uint32_t*)(sKh + n * 16);
                    const uint32_t* krl = (const uint32_t*)(sKl + n * 16);
                    uint32_t kb0 = krh[lane3], kb1 = krh[4 + lane3];
                    uint32_t kl0 = krl[lane3], kl1 = krl[4 + lane3];
                    #pragma unroll
                    for (int i = 0; i < 2; ++i) {
                        mma_bf16(s[i][jj], aqh[i], kb0, kb1);
                        mma_bf16(s[i][jj], aqh[i], kl0, kl1);
                        mma_bf16(s[i][jj], aql[i], kb0, kb1);
                    }
                }
                // softmax piece + pack P fragments
                uint32_t pah[2][4], pal[2][4];
                const bool full = (kbase + 15 <= W0);
                #pragma unroll
                for (int i = 0; i < 2; ++i) {
                    int t0 = W0 + i * 16 + r4, t1 = t0 + 8;
                    #pragma unroll
                    for (int jj = 0; jj < 2; ++jj) {
                        int ub = kbase + jj * 8 + c2;
                        float p0 = __expf(s[i][jj][0] * 0.25f);
                        float p1 = __expf(s[i][jj][1] * 0.25f);
                        float p2 = __expf(s[i][jj][2] * 0.25f);
                        float p3 = __expf(s[i][jj][3] * 0.25f);
                        if (!full) {
                            if (ub > t0)     p0 = 0.f;
                            if (ub + 1 > t0) p1 = 0.f;
                            if (ub > t1)     p2 = 0.f;
                            if (ub + 1 > t1) p3 = 0.f;
                        }
                        lsum[i][0] += p0 + p1;
                        lsum[i][1] += p2 + p3;
                        split2(p0, p1, pah[i][jj * 2 + 0], pal[i][jj * 2 + 0]);
                        split2(p2, p3, pah[i][jj * 2 + 1], pal[i][jj * 2 + 1]);
                    }
                }
                // P @ V for this 16-key chunk
                #pragma unroll
                for (int nt = 0; nt < 2; ++nt) {
                    int n = nt * 8 + r4;
                    const uint32_t* vrh = (const uint32_t*)(sVh + n * 72 + kk * 16);
                    const uint32_t* vrl = (const uint32_t*)(sVl + n * 72 + kk * 16);
                    uint32_t vh0 = vrh[lane3], vh1 = vrh[4 + lane3];
                    uint32_t vl0 = vrl[lane3], vl1 = vrl[4 + lane3];
                    #pragma unroll
                    for (int i = 0; i < 2; ++i) {
                        mma_bf16(o[i][nt], pah[i], vh0, vh1);
                        mma_bf16(o[i][nt], pah[i], vl0, vl1);
                        mma_bf16(o[i][nt], pal[i], vh0, vh1);
                    }
                }
            }
        }
        __syncthreads();
    }

    // normalize + write bf16 hi/lo output
    #pragma unroll
    for (int i = 0; i < 2; ++i) {
        float l0 = lsum[i][0], l1 = lsum[i][1];
        l0 += __shfl_xor_sync(0xffffffffu, l0, 1);
        l0 += __shfl_xor_sync(0xffffffffu, l0, 2);
        l1 += __shfl_xor_sync(0xffffffffu, l1, 1);
        l1 += __shfl_xor_sync(0xffffffffu, l1, 2);
        float i0 = 1.f / l0, i1 = 1.f / l1;
        int row0 = bT + W0 + i * 16 + r4;
        #pragma unroll
        for (int nt = 0; nt < 2; ++nt) {
            int col = (h << 4) + nt * 8 + c2;
            uint32_t hh, ll;
            split2(o[i][nt][0] * i0, o[i][nt][1] * i0, hh, ll);
            *(uint32_t*)(Oh + (size_t)row0 * 128 + col) = hh;
            *(uint32_t*)(Ol + (size_t)row0 * 128 + col) = ll;
            split2(o[i][nt][2] * i1, o[i][nt][3] * i1, hh, ll);
            *(uint32_t*)(Oh + (size_t)(row0 + 8) * 128 + col) = hh;
            *(uint32_t*)(Ol + (size_t)(row0 + 8) * 128 + col) = ll;
        }
    }
}

// ---------------------------------------------------------------------------
extern "C" void kernel_launch(void* const* d_in, const int* in_sizes, int n_in,
                              void* d_out, int out_size)
{
    const float* x   = (const float*)d_in[0];
    const float* Wq  = (const float*)d_in[1];
    const float* bq  = (const float*)d_in[2];
    const float* Wk  = (const float*)d_in[3];
    const float* bk  = (const float*)d_in[4];
    const float* Wv  = (const float*)d_in[5];
    const float* bv  = (const float*)d_in[6];
    const float* Wp  = (const float*)d_in[7];
    const float* bp  = (const float*)d_in[8];
    const float* W1  = (const float*)d_in[9];
    const float* b1  = (const float*)d_in[10];
    const float* W2  = (const float*)d_in[11];
    const float* b2  = (const float*)d_in[12];
    const float* g1  = (const float*)d_in[13];
    const float* be1 = (const float*)d_in[14];
    const float* g2  = (const float*)d_in[15];
    const float* be2 = (const float*)d_in[16];
    float* out = (float*)d_out;

    float *p_qkv, *p_x1, *p_bqkv;
    __nv_bfloat16 *p_xh, *p_xl, *p_ath, *p_atl, *p_x1h, *p_x1l, *p_hih, *p_hil;
    __nv_bfloat16 *p_wqh, *p_wql, *p_wph, *p_wpl, *p_w1h, *p_w1l, *p_w2h, *p_w2l;
    cudaGetSymbolAddress((void**)&p_qkv, g_qkv);
    cudaGetSymbolAddress((void**)&p_x1,  g_x1);
    cudaGetSymbolAddress((void**)&p_bqkv, g_bqkv);
    cudaGetSymbolAddress((void**)&p_xh,  g_xh);  cudaGetSymbolAddress((void**)&p_xl,  g_xl);
    cudaGetSymbolAddress((void**)&p_ath, g_ath); cudaGetSymbolAddress((void**)&p_atl, g_atl);
    cudaGetSymbolAddress((void**)&p_x1h, g_x1h); cudaGetSymbolAddress((void**)&p_x1l, g_x1l);
    cudaGetSymbolAddress((void**)&p_hih, g_hih); cudaGetSymbolAddress((void**)&p_hil, g_hil);
    cudaGetSymbolAddress((void**)&p_wqh, g_wqkv_h); cudaGetSymbolAddress((void**)&p_wql, g_wqkv_l);
    cudaGetSymbolAddress((void**)&p_wph, g_wp_h);   cudaGetSymbolAddress((void**)&p_wpl, g_wp_l);
    cudaGetSymbolAddress((void**)&p_w1h, g_w1_h);   cudaGetSymbolAddress((void**)&p_w1l, g_w1_l);
    cudaGetSymbolAddress((void**)&p_w2h, g_w2_h);   cudaGetSymbolAddress((void**)&p_w2l, g_w2_l);

    cudaFuncSetAttribute(gemm_mma, cudaFuncAttributeMaxDynamicSharedMemorySize, SM_TOTAL);

    // 1. pack weights + split input activations
    pack_kernel<<<256, 256>>>(Wq, bq, Wk, bk, Wv, bv, Wp, W1, W2);
    split_x_kernel<<<BT_TOTAL * DMODEL / 4 / 256, 256>>>(x, p_xh, p_xl);
    // 2. QKV: [16384,128] @ [128,384] -> fp32
    gemm_mma<<<dim3(128, 3), 256, SM_TOTAL>>>(p_xh, p_xl, 128, p_wqh, p_wql,
                                              p_bqkv, nullptr, nullptr, nullptr,
                                              p_qkv, nullptr, nullptr, NQKV, FL_F32);
    // 3. causal attention -> bf16 hi/lo
    attn_mma<<<dim3(8, 128), 128>>>(p_qkv, p_ath, p_atl);
    // 4. proj + bias + resid + LN1 -> fp32 x1 + bf16 hi/lo
    gemm_mma<<<dim3(128, 1), 256, SM_TOTAL>>>(p_ath, p_atl, 128, p_wph, p_wpl,
                                              bp, x, g1, be1,
                                              p_x1, p_x1h, p_x1l, DMODEL, FL_LN | FL_F32 | FL_BF);
    // 5. MLP up + GELU -> bf16 hi/lo
    gemm_mma<<<dim3(128, 4), 256, SM_TOTAL>>>(p_x1h, p_x1l, 128, p_w1h, p_w1l,
                                              b1, nullptr, nullptr, nullptr,
                                              nullptr, p_hih, p_hil, FFDIM, FL_GELU | FL_BF);
    // 6. MLP down (K=512) + bias + resid + LN2 -> out
    gemm_mma<<<dim3(128, 1), 256, SM_TOTAL>>>(p_hih, p_hil, 512, p_w2h, p_w2l,
                                              b2, p_x1, g2, be2,
                                              out, nullptr, nullptr, DMODEL, FL_LN | FL_F32);
}